// round 6
// baseline (speedup 1.0000x reference)
#include <cuda_runtime.h>
#include <cuda_bf16.h>
#include <cstdint>
#include <math.h>

#define NN 50000
#define DD 128
#define EE 625000
#define SCAN_BLOCKS 49                     // ceil(50000/1024)
#define DEG_BLOCKS ((EE + 255) / 256)      // 2442
#define G1_BLOCKS ((NN + 127) / 128)       // 391

// ---------------- scratch (static device allocations) ----------------------
__device__ __nv_bfloat16 g_W1hi[DD * DD];        // lin_w [o][k]
__device__ __nv_bfloat16 g_W1lo[DD * DD];
__device__ __nv_bfloat16 g_W2hi[DD * 3 * DD];    // conv_w packed [o][k*128+i]
__device__ __nv_bfloat16 g_W2lo[DD * 3 * DD];
__device__ float g_transformed[NN * DD];
__device__ float g_conv[NN * DD];
__device__ int   g_deg[NN];                      // zero-maintained across replays
__device__ int   g_rowstart[NN + 1];
__device__ int   g_cursor[NN];
__device__ int   g_csr[EE];
__device__ int   g_bsum[SCAN_BLOCKS];
__device__ int   g_boff[SCAN_BLOCKS];
__device__ int   g_ticket;                       // zero-maintained across replays

#define SMEM_SWIZZLE_128B(b) ((b) ^ (((b) >> 3) & 0x70))

__device__ __forceinline__ uint32_t smem_to_u32(const void* p) {
    uint32_t a;
    asm("{ .reg .u64 t; cvta.to.shared.u64 t, %1; cvt.u32.u64 %0, t; }"
        : "=r"(a) : "l"(p));
    return a;
}
__device__ __forceinline__ void cp_async16(uint32_t saddr, const void* gptr) {
    asm volatile("cp.async.cg.shared.global [%0], [%1], 16;"
                 :: "r"(saddr), "l"(gptr) : "memory");
}
__device__ __forceinline__ void cp_commit() {
    asm volatile("cp.async.commit_group;" ::: "memory");
}
template <int N>
__device__ __forceinline__ void cp_wait() {
    asm volatile("cp.async.wait_group %0;" :: "n"(N) : "memory");
}
__device__ __forceinline__ void ldsm_x4(uint32_t* r, uint32_t addr) {
    asm volatile("ldmatrix.sync.aligned.m8n8.x4.shared.b16 {%0,%1,%2,%3}, [%4];"
                 : "=r"(r[0]), "=r"(r[1]), "=r"(r[2]), "=r"(r[3])
                 : "r"(addr));
}
__device__ __forceinline__ void mma_bf16(float* d, const uint32_t* a,
                                         const uint32_t* b) {
    asm volatile(
        "mma.sync.aligned.m16n8k16.row.col.f32.bf16.bf16.f32 "
        "{%0,%1,%2,%3}, {%4,%5,%6,%7}, {%8,%9}, {%0,%1,%2,%3};"
        : "+f"(d[0]), "+f"(d[1]), "+f"(d[2]), "+f"(d[3])
        : "r"(a[0]), "r"(a[1]), "r"(a[2]), "r"(a[3]), "r"(b[0]), "r"(b[1]));
}
__device__ __forceinline__ void split_bf16(float v, __nv_bfloat16& hi, __nv_bfloat16& lo) {
    hi = __float2bfloat16(v);
    lo = __float2bfloat16(v - __bfloat162float(hi));
}

// ---------------- K1: deg-count (full occupancy) + weight split -------------
__global__ void prep_deg_kernel(const float* __restrict__ lin_w,
                                const float* __restrict__ conv_w,
                                const int* __restrict__ edst) {
    int idx = blockIdx.x * 256 + threadIdx.x;
    if (idx < EE) atomicAdd(&g_deg[edst[idx]], 1);
    if (idx < DD * DD) {
        split_bf16(lin_w[idx], g_W1hi[idx], g_W1lo[idx]);
    } else if (idx < DD * DD + 3 * DD * DD) {
        int t = idx - DD * DD;          // index in [o][k*128+i]
        int o = t / (3 * DD);
        int r = t - o * (3 * DD);
        int k = r >> 7, i = r & 127;
        split_bf16(conv_w[(o * DD + i) * 3 + k], g_W2hi[t], g_W2lo[t]);
    }
}

// ---------------- K2: fused logmap0 + hi/lo split + HMMA GEMM ---------------
static constexpr int ST_AHI = 0;                 // 2 chunk-subtiles x 16KB
static constexpr int ST_ALO = 32768;
static constexpr int ST_WHI = 65536;
static constexpr int ST_WLO = 98304;
static constexpr int SM_BIAS_OFF = 131072;
static constexpr int SM_GEMM_TOTAL = SM_BIAS_OFF + 512;   // 131584

template <int P>
__device__ __forceinline__ void gemm_body_fused(
    int blk, char* smem, uint32_t sb,
    const float* const* planes,
    const __nv_bfloat16* __restrict__ Whi,
    const __nv_bfloat16* __restrict__ Wlo,
    int wstride, float* __restrict__ out,
    const float* __restrict__ bias, float cc) {

    int tid = threadIdx.x;
    int wid = tid >> 5;
    int lane = tid & 31;
    int warp_m = wid & 3;
    int warp_n = wid >> 2;
    int g  = lane >> 3;
    int ri = lane & 7;

    if (tid < 128) ((float*)(smem + SM_BIAS_OFF))[tid] = bias[tid];

    float sc = sqrtf(cc);
    int base = blk * 128;

    float acc[2][8][4];
#pragma unroll
    for (int mi = 0; mi < 2; mi++)
#pragma unroll
        for (int nb = 0; nb < 8; nb++)
#pragma unroll
            for (int q = 0; q < 4; q++) acc[mi][nb][q] = 0.f;

    for (int p = 0; p < P; ++p) {
        // ---- W plane prefetch (overlaps with A conversion) ----
#pragma unroll
        for (int it = 0; it < 8; ++it) {
            int idx = tid + it * 256;          // 0..2047
            int o = idx >> 4, q = idx & 15;    // q: 16B-unit within 256B row
            int cch = q >> 3;
            uint32_t soff = (uint32_t)(cch << 14)
                          + SMEM_SWIZZLE_128B((uint32_t)(o * 128 + (q & 7) * 16));
            size_t gidx = (size_t)o * wstride + p * 128 + q * 8;
            cp_async16(sb + ST_WHI + soff, Whi + gidx);
            cp_async16(sb + ST_WLO + soff, Wlo + gidx);
        }
        cp_commit();

        // ---- A conversion: logmap0 + hi/lo split, registers -> swizzled smem
        const float* plane = planes[p];
        uint32_t soff_base = (uint32_t)((lane >> 4) << 14);
        uint32_t soff_col  = (uint32_t)((lane & 15) * 8);
#pragma unroll
        for (int rr = 0; rr < 16; rr += 2) {
            int row0 = (wid << 4) + rr;
            int row1 = row0 + 1;
            int gn0 = base + row0; if (gn0 >= NN) gn0 = NN - 1;
            int gn1 = base + row1; if (gn1 >= NN) gn1 = NN - 1;
            float4 x0 = ((const float4*)plane)[(size_t)gn0 * 32 + lane];
            float4 x1 = ((const float4*)plane)[(size_t)gn1 * 32 + lane];
            float s0 = fmaf(x0.x, x0.x, fmaf(x0.y, x0.y, fmaf(x0.z, x0.z, x0.w * x0.w)));
            float s1 = fmaf(x1.x, x1.x, fmaf(x1.y, x1.y, fmaf(x1.z, x1.z, x1.w * x1.w)));
#pragma unroll
            for (int off = 16; off; off >>= 1) {
                s0 += __shfl_xor_sync(0xffffffffu, s0, off);
                s1 += __shfl_xor_sync(0xffffffffu, s1, off);
            }
            float xn0 = fmaxf(sqrtf(s0), 1e-15f);
            float xn1 = fmaxf(sqrtf(s1), 1e-15f);
            float a0 = atanhf(fminf(sc * xn0, 1.0f - 1e-5f)) / (sc * xn0);
            float a1 = atanhf(fminf(sc * xn1, 1.0f - 1e-5f)) / (sc * xn1);

            union { __nv_bfloat16 b[4]; uint2 u; } h0, l0, h1, l1;
            float v0[4] = {x0.x * a0, x0.y * a0, x0.z * a0, x0.w * a0};
            float v1[4] = {x1.x * a1, x1.y * a1, x1.z * a1, x1.w * a1};
#pragma unroll
            for (int t = 0; t < 4; t++) {
                split_bf16(v0[t], h0.b[t], l0.b[t]);
                split_bf16(v1[t], h1.b[t], l1.b[t]);
            }
            uint32_t o0 = soff_base + SMEM_SWIZZLE_128B((uint32_t)(row0 * 128) + soff_col);
            uint32_t o1 = soff_base + SMEM_SWIZZLE_128B((uint32_t)(row1 * 128) + soff_col);
            *(uint2*)(smem + ST_AHI + o0) = h0.u;
            *(uint2*)(smem + ST_ALO + o0) = l0.u;
            *(uint2*)(smem + ST_AHI + o1) = h1.u;
            *(uint2*)(smem + ST_ALO + o1) = l1.u;
        }
        cp_wait<0>();
        __syncthreads();

        // ---- MMA over the plane's 2 chunks of 64 k ----
#pragma unroll
        for (int cch = 0; cch < 2; ++cch) {
            uint32_t cb = (uint32_t)(cch << 14);
#pragma unroll
            for (int ks = 0; ks < 4; ++ks) {
                uint32_t a_hi[2][4], a_lo[2][4];
#pragma unroll
                for (int mi = 0; mi < 2; ++mi) {
                    int row = warp_m * 32 + mi * 16 + ((g & 1) << 3) + ri;
                    int kb  = ks * 32 + ((g >> 1) << 4);
                    uint32_t off = cb + SMEM_SWIZZLE_128B((uint32_t)(row * 128 + kb));
                    ldsm_x4(a_hi[mi], sb + ST_AHI + off);
                    ldsm_x4(a_lo[mi], sb + ST_ALO + off);
                }
#pragma unroll
                for (int pp = 0; pp < 3; ++pp) {
                    uint32_t woff = (pp == 1) ? (uint32_t)ST_WLO : (uint32_t)ST_WHI;
                    uint32_t (*af)[4] = (pp == 2) ? a_lo : a_hi;
                    uint32_t b[8][2];
#pragma unroll
                    for (int nb2 = 0; nb2 < 4; ++nb2) {
                        int row = warp_n * 64 + nb2 * 16 + ((g >> 1) << 3) + ri;
                        int kb  = ks * 32 + ((g & 1) << 4);
                        uint32_t off = cb + SMEM_SWIZZLE_128B((uint32_t)(row * 128 + kb));
                        uint32_t r[4];
                        ldsm_x4(r, sb + woff + off);
                        b[nb2 * 2 + 0][0] = r[0];
                        b[nb2 * 2 + 0][1] = r[1];
                        b[nb2 * 2 + 1][0] = r[2];
                        b[nb2 * 2 + 1][1] = r[3];
                    }
#pragma unroll
                    for (int mi = 0; mi < 2; ++mi)
#pragma unroll
                        for (int nb = 0; nb < 8; ++nb)
                            mma_bf16(acc[mi][nb], af[mi], b[nb]);
                }
            }
        }
        __syncthreads();   // buffers reused by next plane
    }

    // ---- epilogue ----
    const float* bias_s = (const float*)(smem + SM_BIAS_OFF);
    int qrow = lane >> 2;
    int qcol = (lane & 3) * 2;
#pragma unroll
    for (int mi = 0; mi < 2; ++mi) {
#pragma unroll
        for (int nb = 0; nb < 8; ++nb) {
            int col = warp_n * 64 + nb * 8 + qcol;
            float b0 = bias_s[col], b1 = bias_s[col + 1];
            int r0 = base + warp_m * 32 + mi * 16 + qrow;
            if (r0 < NN) {
                float2 v0 = make_float2(acc[mi][nb][0] + b0, acc[mi][nb][1] + b1);
                *(float2*)(out + (size_t)r0 * DD + col) = v0;
            }
            int r1 = r0 + 8;
            if (r1 < NN) {
                float2 v1 = make_float2(acc[mi][nb][2] + b0, acc[mi][nb][3] + b1);
                *(float2*)(out + (size_t)r1 * DD + col) = v1;
            }
        }
    }
}

__global__ __launch_bounds__(256)
void gemm_fused_kernel(const float* __restrict__ node,
                       const float* __restrict__ h1,
                       const float* __restrict__ h2,
                       const float* __restrict__ h3,
                       const float* __restrict__ lin_b,
                       const float* __restrict__ conv_b,
                       const float* __restrict__ curv) {
    extern __shared__ char smem[];
    uint32_t sb = smem_to_u32(smem);
    float cc = fabsf(curv[0]);
    if (blockIdx.x < G1_BLOCKS) {
        const float* planes[1] = {node};
        gemm_body_fused<1>(blockIdx.x, smem, sb, planes,
                           g_W1hi, g_W1lo, 128, g_transformed, lin_b, cc);
    } else {
        const float* planes[3] = {h1, h2, h3};
        gemm_body_fused<3>(blockIdx.x - G1_BLOCKS, smem, sb, planes,
                           g_W2hi, g_W2lo, 384, g_conv, conv_b, cc);
    }
}

// ---------------- K3: scan phase 1 + (last block, 1 warp) phase 2 -----------
__global__ __launch_bounds__(1024) void scan12_kernel() {
    __shared__ int wsum[32];
    __shared__ int s_last;
    int tid = threadIdx.x, lane = tid & 31, w = tid >> 5;
    int idx = blockIdx.x * 1024 + tid;
    int v = (idx < NN) ? g_deg[idx] : 0;
    int x = v;
#pragma unroll
    for (int off = 16; off; off >>= 1) x += __shfl_xor_sync(0xffffffffu, x, off);
    if (lane == 0) wsum[w] = x;
    __syncthreads();
    if (w == 0) {
        int z = wsum[lane];
#pragma unroll
        for (int off = 16; off; off >>= 1) z += __shfl_xor_sync(0xffffffffu, z, off);
        if (lane == 0) g_bsum[blockIdx.x] = z;
    }
    __threadfence();
    if (tid == 0) {
        int t = atomicAdd(&g_ticket, 1);
        s_last = (t == (int)gridDim.x - 1);
    }
    __syncthreads();
    if (s_last && w == 0) {
        int v0 = (lane < SCAN_BLOCKS) ? g_bsum[lane] : 0;
        int v1 = (lane + 32 < SCAN_BLOCKS) ? g_bsum[lane + 32] : 0;
        int x0 = v0, x1 = v1;
#pragma unroll
        for (int off = 1; off < 32; off <<= 1) {
            int y0 = __shfl_up_sync(0xffffffffu, x0, off);
            int y1 = __shfl_up_sync(0xffffffffu, x1, off);
            if (lane >= off) { x0 += y0; x1 += y1; }
        }
        int tot0 = __shfl_sync(0xffffffffu, x0, 31);
        x1 += tot0;
        g_boff[lane] = x0 - v0;
        if (lane + 32 < SCAN_BLOCKS) g_boff[lane + 32] = x1 - v1;
        if (lane == 0) { g_rowstart[0] = 0; g_ticket = 0; }
    }
}

// ---------------- K4: block-local scan + offset; zeroes deg for next replay -
__global__ __launch_bounds__(1024) void scan3_kernel() {
    __shared__ int wsum[32];
    int tid = threadIdx.x, lane = tid & 31, w = tid >> 5;
    int idx = blockIdx.x * 1024 + tid;
    int v = (idx < NN) ? g_deg[idx] : 0;
    int x = v;
#pragma unroll
    for (int off = 1; off < 32; off <<= 1) {
        int y = __shfl_up_sync(0xffffffffu, x, off);
        if (lane >= off) x += y;
    }
    if (lane == 31) wsum[w] = x;
    __syncthreads();
    if (w == 0) {
        int z = wsum[lane];
#pragma unroll
        for (int off = 1; off < 32; off <<= 1) {
            int y = __shfl_up_sync(0xffffffffu, z, off);
            if (lane >= off) z += y;
        }
        wsum[lane] = z;
    }
    __syncthreads();
    int incl = x + ((w > 0) ? wsum[w - 1] : 0) + g_boff[blockIdx.x];
    if (idx < NN) {
        g_rowstart[idx + 1] = incl;
        g_cursor[idx]       = incl - v;
        g_deg[idx]          = 0;       // restore zero for next replay
    }
}

// ---------------- K5: place edges into CSR ----------------------------------
__global__ void place_kernel(const int* __restrict__ src,
                             const int* __restrict__ dst) {
    int e = blockIdx.x * blockDim.x + threadIdx.x;
    if (e < EE) {
        int d = dst[e];
        int p = atomicAdd(&g_cursor[d], 1);
        g_csr[p] = src[e];
    }
}

// ---------------- K6: gather-sum + mean + conv add + expmap0 ----------------
__global__ void finalize_kernel(const float* __restrict__ curv,
                                float* __restrict__ out) {
    int n = (blockIdx.x * blockDim.x + threadIdx.x) >> 5;
    int lane = threadIdx.x & 31;
    if (n >= NN) return;

    int s = g_rowstart[n];
    int e = g_rowstart[n + 1];
    const float4* T = (const float4*)g_transformed;

    float4 a = make_float4(0.f, 0.f, 0.f, 0.f);
    int p = s;
    for (; p + 4 <= e; p += 4) {
        int i0 = g_csr[p + 0], i1 = g_csr[p + 1];
        int i2 = g_csr[p + 2], i3 = g_csr[p + 3];
        float4 v0 = T[i0 * 32 + lane];
        float4 v1 = T[i1 * 32 + lane];
        float4 v2 = T[i2 * 32 + lane];
        float4 v3 = T[i3 * 32 + lane];
        a.x += (v0.x + v1.x) + (v2.x + v3.x);
        a.y += (v0.y + v1.y) + (v2.y + v3.y);
        a.z += (v0.z + v1.z) + (v2.z + v3.z);
        a.w += (v0.w + v1.w) + (v2.w + v3.w);
    }
    for (; p < e; ++p) {
        int i0 = g_csr[p];
        float4 v0 = T[i0 * 32 + lane];
        a.x += v0.x; a.y += v0.y; a.z += v0.z; a.w += v0.w;
    }

    float inv = (e > s) ? 1.0f / (float)(e - s) : 0.0f;
    float4 cv = ((const float4*)g_conv)[n * 32 + lane];
    float4 v = make_float4(cv.x + a.x * inv, cv.y + a.y * inv,
                           cv.z + a.z * inv, cv.w + a.w * inv);

    float ss = v.x * v.x + v.y * v.y + v.z * v.z + v.w * v.w;
#pragma unroll
    for (int off = 16; off; off >>= 1) ss += __shfl_xor_sync(0xffffffffu, ss, off);

    float c  = fabsf(curv[0]);
    float sc = sqrtf(c);
    float un = fmaxf(sqrtf(ss), 1e-15f);
    float arg = sc * un;
    float f = tanhf(arg) / arg;

    ((float4*)out)[n * 32 + lane] =
        make_float4(v.x * f, v.y * f, v.z * f, v.w * f);
}

// ---------------- launch ----------------------------------------------------
extern "C" void kernel_launch(void* const* d_in, const int* in_sizes, int n_in,
                              void* d_out, int out_size) {
    const float* node   = (const float*)d_in[0];
    const float* h1     = (const float*)d_in[1];
    const float* h2     = (const float*)d_in[2];
    const float* h3     = (const float*)d_in[3];
    const float* lin_w  = (const float*)d_in[4];
    const float* lin_b  = (const float*)d_in[5];
    const float* conv_w = (const float*)d_in[6];
    const float* conv_b = (const float*)d_in[7];
    const float* curv   = (const float*)d_in[8];
    const int*   esrc   = (const int*)d_in[9];
    const int*   edst   = (const int*)d_in[10];
    float* out = (float*)d_out;

    cudaFuncSetAttribute(gemm_fused_kernel,
                         cudaFuncAttributeMaxDynamicSharedMemorySize, SM_GEMM_TOTAL);

    prep_deg_kernel<<<DEG_BLOCKS, 256>>>(lin_w, conv_w, edst);
    gemm_fused_kernel<<<2 * G1_BLOCKS, 256, SM_GEMM_TOTAL>>>(
        node, h1, h2, h3, lin_b, conv_b, curv);
    scan12_kernel<<<SCAN_BLOCKS, 1024>>>();
    scan3_kernel<<<SCAN_BLOCKS, 1024>>>();
    place_kernel<<<DEG_BLOCKS, 256>>>(esrc, edst);
    finalize_kernel<<<(NN + 7) / 8, 256>>>(curv, out);
}

// round 7
// speedup vs baseline: 1.2308x; 1.2308x over previous
#include <cuda_runtime.h>
#include <cuda_bf16.h>
#include <cstdint>
#include <math.h>

#define NN 50000
#define DD 128
#define EE 625000
#define SCAN_BLOCKS 49                     // ceil(50000/1024)
#define DEG_BLOCKS ((EE + 255) / 256)      // 2442
#define TAN_BLOCKS ((4 * NN) / 8)          // 25000
#define GB_ROWS 256
#define G1_BLOCKS ((NN + GB_ROWS - 1) / GB_ROWS)   // 196

// ---------------- scratch (static device allocations) ----------------------
__device__ __nv_bfloat16 g_A1hi[NN * DD];
__device__ __nv_bfloat16 g_A1lo[NN * DD];
__device__ __nv_bfloat16 g_A2hi[NN * 3 * DD];    // [n][k*128+i]
__device__ __nv_bfloat16 g_A2lo[NN * 3 * DD];
__device__ __nv_bfloat16 g_W1hi[DD * DD];
__device__ __nv_bfloat16 g_W1lo[DD * DD];
__device__ __nv_bfloat16 g_W2hi[DD * 3 * DD];    // [o][k*128+i]
__device__ __nv_bfloat16 g_W2lo[DD * 3 * DD];
__device__ float g_transformed[NN * DD];
__device__ float g_conv[NN * DD];
__device__ int   g_deg[NN];
__device__ int   g_rowstart[NN + 1];
__device__ int   g_cursor[NN];
__device__ int   g_csr[EE];
__device__ int   g_bsum[SCAN_BLOCKS];
__device__ int   g_boff[SCAN_BLOCKS];
__device__ int   g_ticket;

#define SMEM_SWIZZLE_128B(b) ((b) ^ (((b) >> 3) & 0x70))

__device__ __forceinline__ uint32_t smem_to_u32(const void* p) {
    uint32_t a;
    asm("{ .reg .u64 t; cvta.to.shared.u64 t, %1; cvt.u32.u64 %0, t; }"
        : "=r"(a) : "l"(p));
    return a;
}
__device__ __forceinline__ void cp_async16(uint32_t saddr, const void* gptr) {
    asm volatile("cp.async.cg.shared.global [%0], [%1], 16;"
                 :: "r"(saddr), "l"(gptr) : "memory");
}
__device__ __forceinline__ void cp_commit() {
    asm volatile("cp.async.commit_group;" ::: "memory");
}
template <int N>
__device__ __forceinline__ void cp_wait() {
    asm volatile("cp.async.wait_group %0;" :: "n"(N) : "memory");
}
__device__ __forceinline__ void ldsm_x4(uint32_t* r, uint32_t addr) {
    asm volatile("ldmatrix.sync.aligned.m8n8.x4.shared.b16 {%0,%1,%2,%3}, [%4];"
                 : "=r"(r[0]), "=r"(r[1]), "=r"(r[2]), "=r"(r[3])
                 : "r"(addr));
}
__device__ __forceinline__ void mma_bf16(float* d, const uint32_t* a,
                                         const uint32_t* b) {
    asm volatile(
        "mma.sync.aligned.m16n8k16.row.col.f32.bf16.bf16.f32 "
        "{%0,%1,%2,%3}, {%4,%5,%6,%7}, {%8,%9}, {%0,%1,%2,%3};"
        : "+f"(d[0]), "+f"(d[1]), "+f"(d[2]), "+f"(d[3])
        : "r"(a[0]), "r"(a[1]), "r"(a[2]), "r"(a[3]), "r"(b[0]), "r"(b[1]));
}
__device__ __forceinline__ void split_bf16(float v, __nv_bfloat16& hi, __nv_bfloat16& lo) {
    hi = __float2bfloat16(v);
    lo = __float2bfloat16(v - __bfloat162float(hi));
}

// ---------------- K1: prep (zero deg/ticket + pack/split weights) -----------
__global__ void prep_kernel(const float* __restrict__ lin_w,
                            const float* __restrict__ conv_w) {
    int idx = blockIdx.x * blockDim.x + threadIdx.x;   // 0 .. 65535
    if (idx == 0) g_ticket = 0;
    if (idx < NN) g_deg[idx] = 0;
    if (idx < DD * DD) {
        split_bf16(lin_w[idx], g_W1hi[idx], g_W1lo[idx]);
    } else if (idx < DD * DD + 3 * DD * DD) {
        int t = idx - DD * DD;          // target index in [o][k*128+i]
        int o = t / (3 * DD);
        int r = t - o * (3 * DD);
        int k = r >> 7, i = r & 127;
        split_bf16(conv_w[(o * DD + i) * 3 + k], g_W2hi[t], g_W2lo[t]);
    }
}

// ---------------- K2: fused deg-count + logmap0->bf16 hi/lo -----------------
__global__ void tangent_deg_kernel(const float* __restrict__ node,
                                   const float* __restrict__ h1,
                                   const float* __restrict__ h2,
                                   const float* __restrict__ h3,
                                   const float* __restrict__ curv,
                                   const int* __restrict__ edst) {
    if (blockIdx.x < DEG_BLOCKS) {
        int e = blockIdx.x * 256 + threadIdx.x;
        if (e < EE) atomicAdd(&g_deg[edst[e]], 1);
        return;
    }
    int rid  = ((blockIdx.x - DEG_BLOCKS) << 3) + (threadIdx.x >> 5);
    int lane = threadIdx.x & 31;
    if (rid >= 4 * NN) return;

    const float* srcp;
    int n = 0, k = 0;
    bool is_node = (rid < NN);
    if (is_node) {
        n = rid;
        srcp = node + (size_t)n * DD;
    } else {
        int t = rid - NN;
        k = t / NN;
        n = t - k * NN;
        const float* h = (k == 0) ? h1 : (k == 1) ? h2 : h3;
        srcp = h + (size_t)n * DD;
    }

    float4 x = ((const float4*)srcp)[lane];
    float ss = x.x * x.x + x.y * x.y + x.z * x.z + x.w * x.w;
#pragma unroll
    for (int off = 16; off; off >>= 1) ss += __shfl_xor_sync(0xffffffffu, ss, off);

    float c  = fabsf(curv[0]);
    float sc = sqrtf(c);
    float xn  = fmaxf(sqrtf(ss), 1e-15f);
    float arg = fminf(sc * xn, 1.0f - 1e-5f);
    float alpha = atanhf(arg) / (sc * xn);

    float v[4] = {x.x * alpha, x.y * alpha, x.z * alpha, x.w * alpha};
    union { __nv_bfloat16 b[4]; uint2 u; } ph, pl;
#pragma unroll
    for (int t = 0; t < 4; t++) split_bf16(v[t], ph.b[t], pl.b[t]);

    if (is_node) {
        ((uint2*)(g_A1hi + (size_t)n * DD))[lane] = ph.u;
        ((uint2*)(g_A1lo + (size_t)n * DD))[lane] = pl.u;
    } else {
        size_t off = (size_t)n * (3 * DD) + k * DD + lane * 4;
        *(uint2*)(g_A2hi + off) = ph.u;
        *(uint2*)(g_A2lo + off) = pl.u;
    }
}

// ---------------- K3: scan phase 1 + (last block, 1 warp) phase 2 -----------
__global__ __launch_bounds__(1024) void scan12_kernel() {
    __shared__ int wsum[32];
    __shared__ int s_last;
    int tid = threadIdx.x, lane = tid & 31, w = tid >> 5;
    int idx = blockIdx.x * 1024 + tid;
    int v = (idx < NN) ? g_deg[idx] : 0;
    int x = v;
#pragma unroll
    for (int off = 16; off; off >>= 1) x += __shfl_xor_sync(0xffffffffu, x, off);
    if (lane == 0) wsum[w] = x;
    __syncthreads();
    if (w == 0) {
        int z = wsum[lane];
#pragma unroll
        for (int off = 16; off; off >>= 1) z += __shfl_xor_sync(0xffffffffu, z, off);
        if (lane == 0) g_bsum[blockIdx.x] = z;
    }
    __threadfence();
    if (tid == 0) {
        int t = atomicAdd(&g_ticket, 1);
        s_last = (t == (int)gridDim.x - 1);
    }
    __syncthreads();
    if (s_last && w == 0) {
        int v0 = (lane < SCAN_BLOCKS) ? g_bsum[lane] : 0;
        int v1 = (lane + 32 < SCAN_BLOCKS) ? g_bsum[lane + 32] : 0;
        int x0 = v0, x1 = v1;
#pragma unroll
        for (int off = 1; off < 32; off <<= 1) {
            int y0 = __shfl_up_sync(0xffffffffu, x0, off);
            int y1 = __shfl_up_sync(0xffffffffu, x1, off);
            if (lane >= off) { x0 += y0; x1 += y1; }
        }
        int tot0 = __shfl_sync(0xffffffffu, x0, 31);
        x1 += tot0;
        g_boff[lane] = x0 - v0;
        if (lane + 32 < SCAN_BLOCKS) g_boff[lane + 32] = x1 - v1;
        if (lane == 0) g_rowstart[0] = 0;
    }
}

// ---------------- K4: block-local scan + offset -> rowstart / cursor --------
__global__ __launch_bounds__(1024) void scan3_kernel() {
    __shared__ int wsum[32];
    int tid = threadIdx.x, lane = tid & 31, w = tid >> 5;
    int idx = blockIdx.x * 1024 + tid;
    int v = (idx < NN) ? g_deg[idx] : 0;
    int x = v;
#pragma unroll
    for (int off = 1; off < 32; off <<= 1) {
        int y = __shfl_up_sync(0xffffffffu, x, off);
        if (lane >= off) x += y;
    }
    if (lane == 31) wsum[w] = x;
    __syncthreads();
    if (w == 0) {
        int z = wsum[lane];
#pragma unroll
        for (int off = 1; off < 32; off <<= 1) {
            int y = __shfl_up_sync(0xffffffffu, z, off);
            if (lane >= off) z += y;
        }
        wsum[lane] = z;
    }
    __syncthreads();
    int incl = x + ((w > 0) ? wsum[w - 1] : 0) + g_boff[blockIdx.x];
    if (idx < NN) {
        g_rowstart[idx + 1] = incl;
        g_cursor[idx]       = incl - v;
    }
}

// ---------------- K5: place edges into CSR ----------------------------------
__global__ void place_kernel(const int* __restrict__ src,
                             const int* __restrict__ dst) {
    int e = blockIdx.x * blockDim.x + threadIdx.x;
    if (e < EE) {
        int d = dst[e];
        int p = atomicAdd(&g_cursor[d], 1);
        g_csr[p] = src[e];
    }
}

// ---------------- K6: fused HMMA GEMMs, M=256 tiles --------------------------
// smem stage: Ahi 32K | Alo 32K | Whi 16K | Wlo 16K = 96K, double buffered.
static constexpr int ST_AHI = 0;
static constexpr int ST_ALO = 32768;
static constexpr int ST_WHI = 65536;
static constexpr int ST_WLO = 81920;
static constexpr int ST_STRIDE = 98304;
static constexpr int SM_BIAS_OFF = 2 * ST_STRIDE;          // 196608
static constexpr int SM_GEMM_TOTAL = SM_BIAS_OFF + 512;    // 197120

template <int K>
__device__ __forceinline__ void gemm_body(
    int blk, char* smem, uint32_t sb,
    const __nv_bfloat16* Ahi, const __nv_bfloat16* Alo,
    const __nv_bfloat16* Whi, const __nv_bfloat16* Wlo,
    float* out, const float* bias) {
    constexpr int CH = K / 64;
    constexpr int KV = K / 8;

    int tid = threadIdx.x;
    int wid = tid >> 5;
    int lane = tid & 31;
    int warp_m = wid & 3;          // 4 m-warps x 64 rows
    int warp_n = wid >> 2;         // 2 n-warps x 64 cols
    int g  = lane >> 3;
    int ri = lane & 7;

    const uint4* A4hi = (const uint4*)Ahi;
    const uint4* A4lo = (const uint4*)Alo;
    const uint4* W4hi = (const uint4*)Whi;
    const uint4* W4lo = (const uint4*)Wlo;

    if (tid < 128) ((float*)(smem + SM_BIAS_OFF))[tid] = bias[tid];

    int base = blk * GB_ROWS;

    auto prefetch = [&](int c, int buf) {
        uint32_t st = sb + buf * ST_STRIDE;
        // A: 256 rows x 8 u4 (hi & lo)
#pragma unroll
        for (int it = 0; it < 8; ++it) {
            int idx = tid + it * 256;           // 0..2047
            int row = idx >> 3;
            int kq  = idx & 7;
            uint32_t off = SMEM_SWIZZLE_128B((uint32_t)(row * 128 + kq * 16));
            int gn = base + row;
            if (gn >= NN) gn = NN - 1;
            size_t gidx = (size_t)gn * KV + c * 8 + kq;
            cp_async16(st + ST_AHI + off, A4hi + gidx);
            cp_async16(st + ST_ALO + off, A4lo + gidx);
        }
        // W: 128 outs x 8 u4 (hi & lo)
#pragma unroll
        for (int it = 0; it < 4; ++it) {
            int idx = tid + it * 256;           // 0..1023
            int o  = idx >> 3;
            int kq = idx & 7;
            uint32_t off = SMEM_SWIZZLE_128B((uint32_t)(o * 128 + kq * 16));
            size_t widx = (size_t)o * KV + c * 8 + kq;
            cp_async16(st + ST_WHI + off, W4hi + widx);
            cp_async16(st + ST_WLO + off, W4lo + widx);
        }
        cp_commit();
    };

    float acc[4][8][4];
#pragma unroll
    for (int mi = 0; mi < 4; mi++)
#pragma unroll
        for (int nb = 0; nb < 8; nb++)
#pragma unroll
            for (int q = 0; q < 4; q++) acc[mi][nb][q] = 0.f;

    prefetch(0, 0);

    for (int c = 0; c < CH; ++c) {
        if (c + 1 < CH) {
            prefetch(c + 1, (c + 1) & 1);
            cp_wait<1>();
        } else {
            cp_wait<0>();
        }
        __syncthreads();

        uint32_t st = sb + (c & 1) * ST_STRIDE;

#pragma unroll
        for (int ks = 0; ks < 4; ++ks) {
            uint32_t a_hi[4][4], a_lo[4][4];
#pragma unroll
            for (int mi = 0; mi < 4; ++mi) {
                int row = warp_m * 64 + mi * 16 + ((g & 1) << 3) + ri;
                int kb  = ks * 32 + ((g >> 1) << 4);
                uint32_t off = SMEM_SWIZZLE_128B((uint32_t)(row * 128 + kb));
                ldsm_x4(a_hi[mi], st + ST_AHI + off);
                ldsm_x4(a_lo[mi], st + ST_ALO + off);
            }
#pragma unroll
            for (int pp = 0; pp < 3; ++pp) {
                uint32_t woff = (pp == 1) ? (uint32_t)ST_WLO : (uint32_t)ST_WHI;
                uint32_t (*af)[4] = (pp == 2) ? a_lo : a_hi;
                uint32_t b[8][2];
#pragma unroll
                for (int nb2 = 0; nb2 < 4; ++nb2) {
                    int row = warp_n * 64 + nb2 * 16 + ((g >> 1) << 3) + ri;
                    int kb  = ks * 32 + ((g & 1) << 4);
                    uint32_t off = SMEM_SWIZZLE_128B((uint32_t)(row * 128 + kb));
                    uint32_t r[4];
                    ldsm_x4(r, st + woff + off);
                    b[nb2 * 2 + 0][0] = r[0];
                    b[nb2 * 2 + 0][1] = r[1];
                    b[nb2 * 2 + 1][0] = r[2];
                    b[nb2 * 2 + 1][1] = r[3];
                }
#pragma unroll
                for (int mi = 0; mi < 4; ++mi)
#pragma unroll
                    for (int nb = 0; nb < 8; ++nb)
                        mma_bf16(acc[mi][nb], af[mi], b[nb]);
            }
        }
        __syncthreads();
    }

    const float* bias_s = (const float*)(smem + SM_BIAS_OFF);
    int qrow = lane >> 2;
    int qcol = (lane & 3) * 2;
#pragma unroll
    for (int mi = 0; mi < 4; ++mi) {
#pragma unroll
        for (int nb = 0; nb < 8; ++nb) {
            int col = warp_n * 64 + nb * 8 + qcol;
            float b0 = bias_s[col], b1 = bias_s[col + 1];
            int r0 = base + warp_m * 64 + mi * 16 + qrow;
            if (r0 < NN) {
                float2 v0 = make_float2(acc[mi][nb][0] + b0, acc[mi][nb][1] + b1);
                *(float2*)(out + (size_t)r0 * DD + col) = v0;
            }
            int r1 = r0 + 8;
            if (r1 < NN) {
                float2 v1 = make_float2(acc[mi][nb][2] + b0, acc[mi][nb][3] + b1);
                *(float2*)(out + (size_t)r1 * DD + col) = v1;
            }
        }
    }
}

__global__ __launch_bounds__(256, 1)
void gemm_fused_kernel(const float* __restrict__ lin_b,
                       const float* __restrict__ conv_b) {
    extern __shared__ char smem[];
    uint32_t sb = smem_to_u32(smem);
    if (blockIdx.x < G1_BLOCKS) {
        gemm_body<128>(blockIdx.x, smem, sb, g_A1hi, g_A1lo, g_W1hi, g_W1lo,
                       g_transformed, lin_b);
    } else {
        gemm_body<384>(blockIdx.x - G1_BLOCKS, smem, sb, g_A2hi, g_A2lo,
                       g_W2hi, g_W2lo, g_conv, conv_b);
    }
}

// ---------------- K7: gather-sum + mean + conv add + expmap0 ----------------
__global__ void finalize_kernel(const float* __restrict__ curv,
                                float* __restrict__ out) {
    int n = (blockIdx.x * blockDim.x + threadIdx.x) >> 5;
    int lane = threadIdx.x & 31;
    if (n >= NN) return;

    int s = g_rowstart[n];
    int e = g_rowstart[n + 1];
    const float4* T = (const float4*)g_transformed;

    float4 a = make_float4(0.f, 0.f, 0.f, 0.f);
    int p = s;
    for (; p + 4 <= e; p += 4) {
        int i0 = g_csr[p + 0], i1 = g_csr[p + 1];
        int i2 = g_csr[p + 2], i3 = g_csr[p + 3];
        float4 v0 = T[i0 * 32 + lane];
        float4 v1 = T[i1 * 32 + lane];
        float4 v2 = T[i2 * 32 + lane];
        float4 v3 = T[i3 * 32 + lane];
        a.x += (v0.x + v1.x) + (v2.x + v3.x);
        a.y += (v0.y + v1.y) + (v2.y + v3.y);
        a.z += (v0.z + v1.z) + (v2.z + v3.z);
        a.w += (v0.w + v1.w) + (v2.w + v3.w);
    }
    for (; p < e; ++p) {
        int i0 = g_csr[p];
        float4 v0 = T[i0 * 32 + lane];
        a.x += v0.x; a.y += v0.y; a.z += v0.z; a.w += v0.w;
    }

    float inv = (e > s) ? 1.0f / (float)(e - s) : 0.0f;
    float4 cv = ((const float4*)g_conv)[n * 32 + lane];
    float4 v = make_float4(cv.x + a.x * inv, cv.y + a.y * inv,
                           cv.z + a.z * inv, cv.w + a.w * inv);

    float ss = v.x * v.x + v.y * v.y + v.z * v.z + v.w * v.w;
#pragma unroll
    for (int off = 16; off; off >>= 1) ss += __shfl_xor_sync(0xffffffffu, ss, off);

    float c  = fabsf(curv[0]);
    float sc = sqrtf(c);
    float un = fmaxf(sqrtf(ss), 1e-15f);
    float arg = sc * un;
    float f = tanhf(arg) / arg;

    ((float4*)out)[n * 32 + lane] =
        make_float4(v.x * f, v.y * f, v.z * f, v.w * f);
}

// ---------------- launch ----------------------------------------------------
extern "C" void kernel_launch(void* const* d_in, const int* in_sizes, int n_in,
                              void* d_out, int out_size) {
    const float* node   = (const float*)d_in[0];
    const float* h1     = (const float*)d_in[1];
    const float* h2     = (const float*)d_in[2];
    const float* h3     = (const float*)d_in[3];
    const float* lin_w  = (const float*)d_in[4];
    const float* lin_b  = (const float*)d_in[5];
    const float* conv_w = (const float*)d_in[6];
    const float* conv_b = (const float*)d_in[7];
    const float* curv   = (const float*)d_in[8];
    const int*   esrc   = (const int*)d_in[9];
    const int*   edst   = (const int*)d_in[10];
    float* out = (float*)d_out;

    cudaFuncSetAttribute(gemm_fused_kernel,
                         cudaFuncAttributeMaxDynamicSharedMemorySize, SM_GEMM_TOTAL);

    prep_kernel<<<(DD * DD + 3 * DD * DD + 255) / 256, 256>>>(lin_w, conv_w);
    tangent_deg_kernel<<<DEG_BLOCKS + TAN_BLOCKS, 256>>>(node, h1, h2, h3, curv, edst);
    scan12_kernel<<<SCAN_BLOCKS, 1024>>>();
    scan3_kernel<<<SCAN_BLOCKS, 1024>>>();
    place_kernel<<<DEG_BLOCKS, 256>>>(esrc, edst);
    gemm_fused_kernel<<<2 * G1_BLOCKS, 256, SM_GEMM_TOTAL>>>(lin_b, conv_b);
    finalize_kernel<<<(NN + 7) / 8, 256>>>(curv, out);
}

// round 8
// speedup vs baseline: 1.4271x; 1.1594x over previous
#include <cuda_runtime.h>
#include <cuda_bf16.h>
#include <cstdint>
#include <math.h>

#define NN 50000
#define DD 128
#define EE 625000
#define SCAN_BLOCKS 49                     // ceil(50000/1024)
#define DEG_BLOCKS ((EE + 255) / 256)      // 2442
#define TAN_BLOCKS ((4 * NN) / 8)          // 25000
#define G1_BLOCKS ((NN + 127) / 128)       // 391

// ---------------- scratch (static device allocations) ----------------------
__device__ __nv_bfloat16 g_A1hi[NN * DD];
__device__ __nv_bfloat16 g_A1lo[NN * DD];
__device__ __nv_bfloat16 g_A2hi[NN * 3 * DD];    // [n][k*128+i]
__device__ __nv_bfloat16 g_A2lo[NN * 3 * DD];
__device__ __nv_bfloat16 g_W1hi[DD * DD];
__device__ __nv_bfloat16 g_W1lo[DD * DD];
__device__ __nv_bfloat16 g_W2hi[DD * 3 * DD];    // [o][k*128+i]
__device__ __nv_bfloat16 g_W2lo[DD * 3 * DD];
__device__ float g_transformed[NN * DD];
__device__ float g_conv[NN * DD];
__device__ int   g_deg[NN];
__device__ int   g_rowstart[NN + 1];
__device__ int   g_cursor[NN];
__device__ int   g_csr[EE];
__device__ int   g_bsum[SCAN_BLOCKS];
__device__ int   g_boff[SCAN_BLOCKS];
__device__ int   g_ticket;

#define SMEM_SWIZZLE_128B(b) ((b) ^ (((b) >> 3) & 0x70))

__device__ __forceinline__ uint32_t smem_to_u32(const void* p) {
    uint32_t a;
    asm("{ .reg .u64 t; cvta.to.shared.u64 t, %1; cvt.u32.u64 %0, t; }"
        : "=r"(a) : "l"(p));
    return a;
}
__device__ __forceinline__ void cp_async16(uint32_t saddr, const void* gptr) {
    asm volatile("cp.async.cg.shared.global [%0], [%1], 16;"
                 :: "r"(saddr), "l"(gptr) : "memory");
}
__device__ __forceinline__ void cp_commit() {
    asm volatile("cp.async.commit_group;" ::: "memory");
}
template <int N>
__device__ __forceinline__ void cp_wait() {
    asm volatile("cp.async.wait_group %0;" :: "n"(N) : "memory");
}
__device__ __forceinline__ void ldsm_x4(uint32_t* r, uint32_t addr) {
    asm volatile("ldmatrix.sync.aligned.m8n8.x4.shared.b16 {%0,%1,%2,%3}, [%4];"
                 : "=r"(r[0]), "=r"(r[1]), "=r"(r[2]), "=r"(r[3])
                 : "r"(addr));
}
__device__ __forceinline__ void mma_bf16(float* d, const uint32_t* a,
                                         const uint32_t* b) {
    asm volatile(
        "mma.sync.aligned.m16n8k16.row.col.f32.bf16.bf16.f32 "
        "{%0,%1,%2,%3}, {%4,%5,%6,%7}, {%8,%9}, {%0,%1,%2,%3};"
        : "+f"(d[0]), "+f"(d[1]), "+f"(d[2]), "+f"(d[3])
        : "r"(a[0]), "r"(a[1]), "r"(a[2]), "r"(a[3]), "r"(b[0]), "r"(b[1]));
}
__device__ __forceinline__ void split_bf16(float v, __nv_bfloat16& hi, __nv_bfloat16& lo) {
    hi = __float2bfloat16(v);
    lo = __float2bfloat16(v - __bfloat162float(hi));
}

// ---------------- K1: prep (zero deg/ticket + pack/split weights) -----------
__global__ void prep_kernel(const float* __restrict__ lin_w,
                            const float* __restrict__ conv_w) {
    int idx = blockIdx.x * blockDim.x + threadIdx.x;   // 0 .. 65535
    if (idx == 0) g_ticket = 0;
    if (idx < NN) g_deg[idx] = 0;
    if (idx < DD * DD) {
        split_bf16(lin_w[idx], g_W1hi[idx], g_W1lo[idx]);
    } else if (idx < DD * DD + 3 * DD * DD) {
        int t = idx - DD * DD;          // target index in [o][k*128+i]
        int o = t / (3 * DD);
        int r = t - o * (3 * DD);
        int k = r >> 7, i = r & 127;
        split_bf16(conv_w[(o * DD + i) * 3 + k], g_W2hi[t], g_W2lo[t]);
    }
}

// ---------------- K2: fused deg-count + logmap0->bf16 hi/lo -----------------
__global__ void tangent_deg_kernel(const float* __restrict__ node,
                                   const float* __restrict__ h1,
                                   const float* __restrict__ h2,
                                   const float* __restrict__ h3,
                                   const float* __restrict__ curv,
                                   const int* __restrict__ edst) {
    if (blockIdx.x < DEG_BLOCKS) {
        int e = blockIdx.x * 256 + threadIdx.x;
        if (e < EE) atomicAdd(&g_deg[edst[e]], 1);
        return;
    }
    int rid  = ((blockIdx.x - DEG_BLOCKS) << 3) + (threadIdx.x >> 5);
    int lane = threadIdx.x & 31;
    if (rid >= 4 * NN) return;

    const float* srcp;
    int n = 0, k = 0;
    bool is_node = (rid < NN);
    if (is_node) {
        n = rid;
        srcp = node + (size_t)n * DD;
    } else {
        int t = rid - NN;
        k = t / NN;
        n = t - k * NN;
        const float* h = (k == 0) ? h1 : (k == 1) ? h2 : h3;
        srcp = h + (size_t)n * DD;
    }

    float4 x = ((const float4*)srcp)[lane];
    float ss = x.x * x.x + x.y * x.y + x.z * x.z + x.w * x.w;
#pragma unroll
    for (int off = 16; off; off >>= 1) ss += __shfl_xor_sync(0xffffffffu, ss, off);

    float c  = fabsf(curv[0]);
    float sc = sqrtf(c);
    float xn  = fmaxf(sqrtf(ss), 1e-15f);
    float arg = fminf(sc * xn, 1.0f - 1e-5f);
    float alpha = atanhf(arg) / (sc * xn);

    float v[4] = {x.x * alpha, x.y * alpha, x.z * alpha, x.w * alpha};
    union { __nv_bfloat16 b[4]; uint2 u; } ph, pl;
#pragma unroll
    for (int t = 0; t < 4; t++) split_bf16(v[t], ph.b[t], pl.b[t]);

    if (is_node) {
        ((uint2*)(g_A1hi + (size_t)n * DD))[lane] = ph.u;
        ((uint2*)(g_A1lo + (size_t)n * DD))[lane] = pl.u;
    } else {
        size_t off = (size_t)n * (3 * DD) + k * DD + lane * 4;
        *(uint2*)(g_A2hi + off) = ph.u;
        *(uint2*)(g_A2lo + off) = pl.u;
    }
}

// ---------------- K3: scan phase 1 + (last block, 1 warp) phase 2 -----------
__global__ __launch_bounds__(1024) void scan12_kernel() {
    __shared__ int wsum[32];
    __shared__ int s_last;
    int tid = threadIdx.x, lane = tid & 31, w = tid >> 5;
    int idx = blockIdx.x * 1024 + tid;
    int v = (idx < NN) ? g_deg[idx] : 0;
    int x = v;
#pragma unroll
    for (int off = 16; off; off >>= 1) x += __shfl_xor_sync(0xffffffffu, x, off);
    if (lane == 0) wsum[w] = x;
    __syncthreads();
    if (w == 0) {
        int z = wsum[lane];
#pragma unroll
        for (int off = 16; off; off >>= 1) z += __shfl_xor_sync(0xffffffffu, z, off);
        if (lane == 0) g_bsum[blockIdx.x] = z;
    }
    __threadfence();
    if (tid == 0) {
        int t = atomicAdd(&g_ticket, 1);
        s_last = (t == (int)gridDim.x - 1);
    }
    __syncthreads();
    if (s_last && w == 0) {
        int v0 = (lane < SCAN_BLOCKS) ? g_bsum[lane] : 0;
        int v1 = (lane + 32 < SCAN_BLOCKS) ? g_bsum[lane + 32] : 0;
        int x0 = v0, x1 = v1;
#pragma unroll
        for (int off = 1; off < 32; off <<= 1) {
            int y0 = __shfl_up_sync(0xffffffffu, x0, off);
            int y1 = __shfl_up_sync(0xffffffffu, x1, off);
            if (lane >= off) { x0 += y0; x1 += y1; }
        }
        int tot0 = __shfl_sync(0xffffffffu, x0, 31);
        x1 += tot0;
        g_boff[lane] = x0 - v0;
        if (lane + 32 < SCAN_BLOCKS) g_boff[lane + 32] = x1 - v1;
        if (lane == 0) g_rowstart[0] = 0;
    }
}

// ---------------- K4: block-local scan + offset -> rowstart / cursor --------
__global__ __launch_bounds__(1024) void scan3_kernel() {
    __shared__ int wsum[32];
    int tid = threadIdx.x, lane = tid & 31, w = tid >> 5;
    int idx = blockIdx.x * 1024 + tid;
    int v = (idx < NN) ? g_deg[idx] : 0;
    int x = v;
#pragma unroll
    for (int off = 1; off < 32; off <<= 1) {
        int y = __shfl_up_sync(0xffffffffu, x, off);
        if (lane >= off) x += y;
    }
    if (lane == 31) wsum[w] = x;
    __syncthreads();
    if (w == 0) {
        int z = wsum[lane];
#pragma unroll
        for (int off = 1; off < 32; off <<= 1) {
            int y = __shfl_up_sync(0xffffffffu, z, off);
            if (lane >= off) z += y;
        }
        wsum[lane] = z;
    }
    __syncthreads();
    int incl = x + ((w > 0) ? wsum[w - 1] : 0) + g_boff[blockIdx.x];
    if (idx < NN) {
        g_rowstart[idx + 1] = incl;
        g_cursor[idx]       = incl - v;
    }
}

// ---------------- K5: place edges into CSR ----------------------------------
__global__ void place_kernel(const int* __restrict__ src,
                             const int* __restrict__ dst) {
    int e = blockIdx.x * blockDim.x + threadIdx.x;
    if (e < EE) {
        int d = dst[e];
        int p = atomicAdd(&g_cursor[d], 1);
        g_csr[p] = src[e];
    }
}

// ---------------- K6: fused HMMA GEMMs (R5 M=128 version) --------------------
static constexpr int ST_AHI = 0;
static constexpr int ST_ALO = 16384;
static constexpr int ST_WHI = 32768;
static constexpr int ST_WLO = 49152;
static constexpr int ST_STRIDE = 65536;
static constexpr int SM_BIAS_OFF = 2 * ST_STRIDE;          // 131072
static constexpr int SM_GEMM_TOTAL = SM_BIAS_OFF + 512;    // 131584

template <int K>
__device__ __forceinline__ void gemm_body(
    int blk, char* smem, uint32_t sb,
    const __nv_bfloat16* Ahi, const __nv_bfloat16* Alo,
    const __nv_bfloat16* Whi, const __nv_bfloat16* Wlo,
    float* out, const float* bias) {
    constexpr int CH = K / 64;
    constexpr int KV = K / 8;

    int tid = threadIdx.x;
    int wid = tid >> 5;
    int lane = tid & 31;
    int warp_m = wid & 3;
    int warp_n = wid >> 2;
    int g  = lane >> 3;
    int ri = lane & 7;

    const uint4* A4hi = (const uint4*)Ahi;
    const uint4* A4lo = (const uint4*)Alo;
    const uint4* W4hi = (const uint4*)Whi;
    const uint4* W4lo = (const uint4*)Wlo;

    if (tid < 128) ((float*)(smem + SM_BIAS_OFF))[tid] = bias[tid];

    int base = blk * 128;

    auto prefetch = [&](int c, int buf) {
        uint32_t st = sb + buf * ST_STRIDE;
#pragma unroll
        for (int it = 0; it < 4; ++it) {
            int idx = tid + it * 256;
            int row = idx >> 3;
            int kq  = idx & 7;
            uint32_t off = SMEM_SWIZZLE_128B((uint32_t)(row * 128 + kq * 16));
            int gn = base + row;
            if (gn >= NN) gn = NN - 1;
            size_t gidx = (size_t)gn * KV + c * 8 + kq;
            size_t widx = (size_t)row * KV + c * 8 + kq;
            cp_async16(st + ST_AHI + off, A4hi + gidx);
            cp_async16(st + ST_ALO + off, A4lo + gidx);
            cp_async16(st + ST_WHI + off, W4hi + widx);
            cp_async16(st + ST_WLO + off, W4lo + widx);
        }
        cp_commit();
    };

    float acc[2][8][4];
#pragma unroll
    for (int mi = 0; mi < 2; mi++)
#pragma unroll
        for (int nb = 0; nb < 8; nb++)
#pragma unroll
            for (int q = 0; q < 4; q++) acc[mi][nb][q] = 0.f;

    prefetch(0, 0);

    for (int c = 0; c < CH; ++c) {
        if (c + 1 < CH) {
            prefetch(c + 1, (c + 1) & 1);
            cp_wait<1>();
        } else {
            cp_wait<0>();
        }
        __syncthreads();

        uint32_t st = sb + (c & 1) * ST_STRIDE;

#pragma unroll
        for (int ks = 0; ks < 4; ++ks) {
            uint32_t a_hi[2][4], a_lo[2][4];
#pragma unroll
            for (int mi = 0; mi < 2; ++mi) {
                int row = warp_m * 32 + mi * 16 + ((g & 1) << 3) + ri;
                int kb  = ks * 32 + ((g >> 1) << 4);
                uint32_t off = SMEM_SWIZZLE_128B((uint32_t)(row * 128 + kb));
                ldsm_x4(a_hi[mi], st + ST_AHI + off);
                ldsm_x4(a_lo[mi], st + ST_ALO + off);
            }
#pragma unroll
            for (int pp = 0; pp < 3; ++pp) {
                uint32_t woff = (pp == 1) ? (uint32_t)ST_WLO : (uint32_t)ST_WHI;
                uint32_t (*af)[4] = (pp == 2) ? a_lo : a_hi;
                uint32_t b[8][2];
#pragma unroll
                for (int nb2 = 0; nb2 < 4; ++nb2) {
                    int row = warp_n * 64 + nb2 * 16 + ((g >> 1) << 3) + ri;
                    int kb  = ks * 32 + ((g & 1) << 4);
                    uint32_t off = SMEM_SWIZZLE_128B((uint32_t)(row * 128 + kb));
                    uint32_t r[4];
                    ldsm_x4(r, st + woff + off);
                    b[nb2 * 2 + 0][0] = r[0];
                    b[nb2 * 2 + 0][1] = r[1];
                    b[nb2 * 2 + 1][0] = r[2];
                    b[nb2 * 2 + 1][1] = r[3];
                }
#pragma unroll
                for (int mi = 0; mi < 2; ++mi)
#pragma unroll
                    for (int nb = 0; nb < 8; ++nb)
                        mma_bf16(acc[mi][nb], af[mi], b[nb]);
            }
        }
        __syncthreads();
    }

    const float* bias_s = (const float*)(smem + SM_BIAS_OFF);
    int qrow = lane >> 2;
    int qcol = (lane & 3) * 2;
#pragma unroll
    for (int mi = 0; mi < 2; ++mi) {
#pragma unroll
        for (int nb = 0; nb < 8; ++nb) {
            int col = warp_n * 64 + nb * 8 + qcol;
            float b0 = bias_s[col], b1 = bias_s[col + 1];
            int r0 = base + warp_m * 32 + mi * 16 + qrow;
            if (r0 < NN) {
                float2 v0 = make_float2(acc[mi][nb][0] + b0, acc[mi][nb][1] + b1);
                *(float2*)(out + (size_t)r0 * DD + col) = v0;
            }
            int r1 = r0 + 8;
            if (r1 < NN) {
                float2 v1 = make_float2(acc[mi][nb][2] + b0, acc[mi][nb][3] + b1);
                *(float2*)(out + (size_t)r1 * DD + col) = v1;
            }
        }
    }
}

__global__ __launch_bounds__(256)
void gemm_fused_kernel(const float* __restrict__ lin_b,
                       const float* __restrict__ conv_b) {
    extern __shared__ char smem[];
    uint32_t sb = smem_to_u32(smem);
    if (blockIdx.x < G1_BLOCKS) {
        gemm_body<128>(blockIdx.x, smem, sb, g_A1hi, g_A1lo, g_W1hi, g_W1lo,
                       g_transformed, lin_b);
    } else {
        gemm_body<384>(blockIdx.x - G1_BLOCKS, smem, sb, g_A2hi, g_A2lo,
                       g_W2hi, g_W2lo, g_conv, conv_b);
    }
}

// ---------------- K7: gather-sum + mean + conv add + expmap0 ----------------
__global__ void finalize_kernel(const float* __restrict__ curv,
                                float* __restrict__ out) {
    int n = (blockIdx.x * blockDim.x + threadIdx.x) >> 5;
    int lane = threadIdx.x & 31;
    if (n >= NN) return;

    int s = g_rowstart[n];
    int e = g_rowstart[n + 1];
    const float4* T = (const float4*)g_transformed;

    float4 a = make_float4(0.f, 0.f, 0.f, 0.f);
    int p = s;
    for (; p + 4 <= e; p += 4) {
        int i0 = g_csr[p + 0], i1 = g_csr[p + 1];
        int i2 = g_csr[p + 2], i3 = g_csr[p + 3];
        float4 v0 = T[i0 * 32 + lane];
        float4 v1 = T[i1 * 32 + lane];
        float4 v2 = T[i2 * 32 + lane];
        float4 v3 = T[i3 * 32 + lane];
        a.x += (v0.x + v1.x) + (v2.x + v3.x);
        a.y += (v0.y + v1.y) + (v2.y + v3.y);
        a.z += (v0.z + v1.z) + (v2.z + v3.z);
        a.w += (v0.w + v1.w) + (v2.w + v3.w);
    }
    for (; p < e; ++p) {
        int i0 = g_csr[p];
        float4 v0 = T[i0 * 32 + lane];
        a.x += v0.x; a.y += v0.y; a.z += v0.z; a.w += v0.w;
    }

    float inv = (e > s) ? 1.0f / (float)(e - s) : 0.0f;
    float4 cv = ((const float4*)g_conv)[n * 32 + lane];
    float4 v = make_float4(cv.x + a.x * inv, cv.y + a.y * inv,
                           cv.z + a.z * inv, cv.w + a.w * inv);

    float ss = v.x * v.x + v.y * v.y + v.z * v.z + v.w * v.w;
#pragma unroll
    for (int off = 16; off; off >>= 1) ss += __shfl_xor_sync(0xffffffffu, ss, off);

    float c  = fabsf(curv[0]);
    float sc = sqrtf(c);
    float un = fmaxf(sqrtf(ss), 1e-15f);
    float arg = sc * un;
    float f = tanhf(arg) / arg;

    ((float4*)out)[n * 32 + lane] =
        make_float4(v.x * f, v.y * f, v.z * f, v.w * f);
}

// ---------------- launch: fork CSR branch to a second stream ----------------
extern "C" void kernel_launch(void* const* d_in, const int* in_sizes, int n_in,
                              void* d_out, int out_size) {
    const float* node   = (const float*)d_in[0];
    const float* h1     = (const float*)d_in[1];
    const float* h2     = (const float*)d_in[2];
    const float* h3     = (const float*)d_in[3];
    const float* lin_w  = (const float*)d_in[4];
    const float* lin_b  = (const float*)d_in[5];
    const float* conv_w = (const float*)d_in[6];
    const float* conv_b = (const float*)d_in[7];
    const float* curv   = (const float*)d_in[8];
    const int*   esrc   = (const int*)d_in[9];
    const int*   edst   = (const int*)d_in[10];
    float* out = (float*)d_out;

    static cudaStream_t s2 = nullptr;
    static cudaEvent_t evA = nullptr, evB = nullptr;
    if (s2 == nullptr) {
        cudaStreamCreateWithFlags(&s2, cudaStreamNonBlocking);
        cudaEventCreateWithFlags(&evA, cudaEventDisableTiming);
        cudaEventCreateWithFlags(&evB, cudaEventDisableTiming);
        cudaFuncSetAttribute(gemm_fused_kernel,
                             cudaFuncAttributeMaxDynamicSharedMemorySize,
                             SM_GEMM_TOTAL);
    }

    prep_kernel<<<(DD * DD + 3 * DD * DD + 255) / 256, 256>>>(lin_w, conv_w);
    tangent_deg_kernel<<<DEG_BLOCKS + TAN_BLOCKS, 256>>>(node, h1, h2, h3, curv, edst);

    // fork: CSR pipeline on s2, GEMM on main stream
    cudaEventRecord(evA, 0);
    cudaStreamWaitEvent(s2, evA, 0);

    scan12_kernel<<<SCAN_BLOCKS, 1024, 0, s2>>>();
    scan3_kernel<<<SCAN_BLOCKS, 1024, 0, s2>>>();
    place_kernel<<<DEG_BLOCKS, 256, 0, s2>>>(esrc, edst);

    gemm_fused_kernel<<<2 * G1_BLOCKS, 256, SM_GEMM_TOTAL>>>(lin_b, conv_b);

    // join
    cudaEventRecord(evB, s2);
    cudaStreamWaitEvent(0, evB, 0);

    finalize_kernel<<<(NN + 7) / 8, 256>>>(curv, out);
}